// round 17
// baseline (speedup 1.0000x reference)
#include <cuda_runtime.h>
#include <cuda_bf16.h>
#include <cuda_fp16.h>
#include <cstdint>

#define SEQ    256
#define BATCH  32
#define REC    16
#define EMB    32
#define VOCAB  32000
#define NROWS  (SEQ * BATCH)   // 8192
#define NPAIR  (VOCAB / 16)    // 2000 column-pairs

// tiling for k_sum / k_out: 25-pair smem slice x 256 rows (8 warps x 32)
#define OPAIRS 25
#define NCG    (NPAIR / OPAIRS)   // 80 column groups
#define ORPB   256
#define NRG    (NROWS / ORPB)     // 32 row groups

// ---- scratch ----
__device__ float          g_Apre[NROWS * REC];      // prescaled by 2*log2(e)
__device__ __nv_bfloat16  g_hidden[NROWS * REC];    // hidden, bf16 (pass 2)
__device__ __half         g_hiddenLh[NROWS * REC];  // hidden * log2(e), fp16 (pass 1)
__device__ uint4          g_Vq[NPAIR * 8 * 4];      // permuted V, bf16 (pass 2)
__device__ uint4          g_Vqh[NPAIR * 8 * 4];     // permuted V, fp16 (pass 1)
__device__ float          g_part[NCG][NROWS];       // per-colgroup partial sumexp
__device__ float          g_rowc[NROWS];            // -ln(sum)
__device__ int            g_cnt[NRG];               // colgroup completion counters

__device__ __forceinline__ float ex2f(float x) { float y; asm("ex2.approx.f32 %0, %1;" : "=f"(y) : "f"(x)); return y; }
__device__ __forceinline__ float lg2f(float x) { float y; asm("lg2.approx.f32 %0, %1;" : "=f"(y) : "f"(x)); return y; }
__device__ __forceinline__ float rcpf(float x) { float y; asm("rcp.approx.f32 %0, %1;" : "=f"(y) : "f"(x)); return y; }

#define L2E 1.4426950408889634f
#define LN2 0.6931471805599453f

// bf16 MMA, fp32 accum (pass 2): d = A*B + {nc0,nc0,nc1,nc1}
__device__ __forceinline__ void mma16816c(float d[4], const uint32_t a[4], uint32_t b0, uint32_t b1,
                                          float nc0, float nc1) {
    asm("mma.sync.aligned.m16n8k16.row.col.f32.bf16.bf16.f32 "
        "{%0,%1,%2,%3}, {%4,%5,%6,%7}, {%8,%9}, {%10,%11,%12,%13};"
        : "=f"(d[0]), "=f"(d[1]), "=f"(d[2]), "=f"(d[3])
        : "r"(a[0]), "r"(a[1]), "r"(a[2]), "r"(a[3]),
          "r"(b0), "r"(b1),
          "f"(nc0), "f"(nc0), "f"(nc1), "f"(nc1));
}

// fp16 MMA, fp16 accum (pass 1): d0 = rows r, d1 = rows r+8 (packed f16x2)
__device__ __forceinline__ void mma16816h(uint32_t& d0, uint32_t& d1, const uint32_t a[4],
                                          uint32_t b0, uint32_t b1) {
    asm("mma.sync.aligned.m16n8k16.row.col.f16.f16.f16.f16 "
        "{%0,%1}, {%2,%3,%4,%5}, {%6,%7}, {%8,%9};"
        : "=r"(d0), "=r"(d1)
        : "r"(a[0]), "r"(a[1]), "r"(a[2]), "r"(a[3]),
          "r"(b0), "r"(b1), "r"(0u), "r"(0u));
}

// 2^x on a packed f16x2 register (inputs already log2-domain)
__device__ __forceinline__ __half2 h2ex2r(uint32_t u) {
    uint32_t r;
    asm("ex2.approx.f16x2 %0, %1;" : "=r"(r) : "r"(u));
    return *reinterpret_cast<__half2*>(&r);
}

// ---------------- Kernel 1: A_pre (prescaled) + counter reset ----------------
#define PREP_ABLK (NROWS * REC / 256)    // 512
__global__ void k_prepA(const int* __restrict__ tok, const float* __restrict__ emb,
                        const float* __restrict__ U,
                        const float* __restrict__ b1, const float* __restrict__ b2) {
    if (blockIdx.x == 0 && threadIdx.x < NRG) g_cnt[threadIdx.x] = 0;
    int i = blockIdx.x * 256 + threadIdx.x;
    int rid = i >> 4, r = i & 15;
    int tk  = tok[rid];
    const float4* e4 = (const float4*)(emb + (size_t)tk * EMB);
    const float4* u4 = (const float4*)(U + r * EMB);
    float acc = b1[r] + b2[r];
    #pragma unroll
    for (int k = 0; k < EMB / 4; k++) {
        float4 e = e4[k], u = u4[k];
        acc = fmaf(e.x, u.x, acc);
        acc = fmaf(e.y, u.y, acc);
        acc = fmaf(e.z, u.z, acc);
        acc = fmaf(e.w, u.w, acc);
    }
    g_Apre[i] = acc * (2.0f * L2E);
}

// ---------------- Kernel 2 (mixed): V permute (blocks 0-124) + rnn (blocks 125-140) ----
#define MIX_VBLK (VOCAB / 256)           // 125
#define MIX_NBLK (MIX_VBLK + BATCH / 2)  // 141
__global__ void k_mix(const float* __restrict__ V, const float* __restrict__ W,
                      const float* __restrict__ h0v) {
    if (blockIdx.x < MIX_VBLK) {
        // ---- V permute: one vocab column per thread, both precisions ----
        int c = blockIdx.x * 256 + threadIdx.x;
        const float4* v4 = (const float4*)(V + (size_t)c * REC);
        float4 q0 = v4[0], q1 = v4[1], q2 = v4[2], q3 = v4[3];
        float vv[16] = {q0.x,q0.y,q0.z,q0.w, q1.x,q1.y,q1.z,q1.w,
                        q2.x,q2.y,q2.z,q2.w, q3.x,q3.y,q3.z,q3.w};
        uint32_t pb[8], ph[8];
        #pragma unroll
        for (int j = 0; j < 8; j++) {
            __nv_bfloat162 b2v = __floats2bfloat162_rn(vv[2*j], vv[2*j+1]);
            __half2        h2v = __floats2half2_rn(vv[2*j], vv[2*j+1]);
            pb[j] = *reinterpret_cast<uint32_t*>(&b2v);
            ph[j] = *reinterpret_cast<uint32_t*>(&h2v);
        }
        int p    = c >> 4;
        int w16  = c & 15;
        int tile = (w16 >> 1) & 1;
        int n    = ((w16 >> 2) << 1) | (w16 & 1);
        uint32_t* db = (uint32_t*)g_Vq;
        uint32_t* dh = (uint32_t*)g_Vqh;
        #pragma unroll
        for (int t = 0; t < 4; t++) {
            int slot = (((p * 8 + n) * 4 + t) << 2) + tile * 2;
            *(uint2*)(db + slot) = make_uint2(pb[t], pb[t + 4]);
            *(uint2*)(dh + slot) = make_uint2(ph[t], ph[t + 4]);
        }
    } else {
        // ---- serial recurrence: 32 threads, 2 batches per block ----
        if (threadIdx.x >= 32) return;
        int lane = threadIdx.x;
        int b = (blockIdx.x - MIX_VBLK) * 2 + (lane >> 4);
        int r = lane & 15;
        float w[REC];
        #pragma unroll
        for (int j = 0; j < REC; j++) w[j] = W[r * REC + j] * (2.0f * L2E);
        float h = h0v[r];
        g_hidden[b * REC + r]   = __float2bfloat16(h);
        g_hiddenLh[b * REC + r] = __float2half(h * L2E);
        float anext = g_Apre[b * REC + r];
        for (int t = 0; t < SEQ - 1; t++) {
            float a = anext;
            if (t < SEQ - 2) anext = g_Apre[((t + 1) * BATCH + b) * REC + r];
            float s0 = a, s1 = 0.f, s2 = 0.f, s3 = 0.f;
            #pragma unroll
            for (int j = 0; j < REC; j += 4) {
                float h0_ = __shfl_sync(0xffffffffu, h, j,     16);
                float h1_ = __shfl_sync(0xffffffffu, h, j + 1, 16);
                float h2_ = __shfl_sync(0xffffffffu, h, j + 2, 16);
                float h3_ = __shfl_sync(0xffffffffu, h, j + 3, 16);
                s0 = fmaf(h0_, w[j],     s0);
                s1 = fmaf(h1_, w[j + 1], s1);
                s2 = fmaf(h2_, w[j + 2], s2);
                s3 = fmaf(h3_, w[j + 3], s3);
            }
            float z  = (s0 + s1) + (s2 + s3);   // already 2x*log2(e)
            float ez = ex2f(z);
            h = 1.0f - 2.0f * rcpf(ez + 1.0f);
            int idx = ((t + 1) * BATCH + b) * REC + r;
            g_hidden[idx]   = __float2bfloat16(h);
            g_hiddenLh[idx] = __float2half(h * L2E);
        }
    }
}

// ---------------- Kernel 3: smem-staged fp16-MMA sum exp + fused last-block reduce ----
// grid (NCG=80, NRG=32); block stages 25 fp16 pairs once, each warp owns 32 rows.
__global__ void __launch_bounds__(256, 5) k_sum() {
    __shared__ uint4 sVq[OPAIRS * 32];
    __shared__ int sLast;

    const int lane = threadIdx.x & 31, warp = threadIdx.x >> 5;
    const int g = lane >> 2, t = lane & 3;
    const int cg    = blockIdx.x;
    const int rg    = blockIdx.y;
    const int rbase = rg * ORPB + warp * 32;

    {
        const uint4* src = g_Vqh + cg * (OPAIRS * 32);
        for (int i = threadIdx.x; i < OPAIRS * 32; i += 256) sVq[i] = src[i];
    }

    uint32_t a[2][4];
    const uint32_t* H = (const uint32_t*)g_hiddenLh;
    #pragma unroll
    for (int f = 0; f < 2; f++) {
        int r0 = rbase + f * 16 + g;
        a[f][0] = H[r0 * 8 + t];
        a[f][1] = H[(r0 + 8) * 8 + t];
        a[f][2] = H[r0 * 8 + t + 4];
        a[f][3] = H[(r0 + 8) * 8 + t + 4];
    }
    __syncthreads();

    float s[2][2];
    __half2 hacc[2][2];
    #pragma unroll
    for (int f = 0; f < 2; f++) {
        s[f][0] = s[f][1] = 0.f;
        hacc[f][0] = hacc[f][1] = __float2half2_rn(0.f);
    }

    uint4 b = sVq[lane];
    #pragma unroll 1
    for (int blk = 0; blk < 5; blk++) {           // flush every 5 pairs
        #pragma unroll
        for (int q = 0; q < 5; q++) {
            int pl = blk * 5 + q;
            uint4 bn;
            if (pl + 1 < OPAIRS) bn = sVq[(pl + 1) * 32 + lane];
            #pragma unroll
            for (int f = 0; f < 2; f++) {
                uint32_t d0, d1, e0, e1;
                mma16816h(d0, d1, a[f], b.x, b.y);   // tile 0
                mma16816h(e0, e1, a[f], b.z, b.w);   // tile 1
                hacc[f][0] = __hadd2(hacc[f][0], h2ex2r(d0));
                hacc[f][0] = __hadd2(hacc[f][0], h2ex2r(e0));
                hacc[f][1] = __hadd2(hacc[f][1], h2ex2r(d1));
                hacc[f][1] = __hadd2(hacc[f][1], h2ex2r(e1));
            }
            b = bn;
        }
        #pragma unroll
        for (int f = 0; f < 2; f++) {
            float2 f0 = __half22float2(hacc[f][0]);
            float2 f1 = __half22float2(hacc[f][1]);
            s[f][0] += f0.x + f0.y;
            s[f][1] += f1.x + f1.y;
            hacc[f][0] = hacc[f][1] = __float2half2_rn(0.f);
        }
    }
    #pragma unroll
    for (int f = 0; f < 2; f++) {
        #pragma unroll
        for (int m = 1; m <= 2; m <<= 1) {
            s[f][0] += __shfl_xor_sync(0xffffffffu, s[f][0], m);
            s[f][1] += __shfl_xor_sync(0xffffffffu, s[f][1], m);
        }
        if (t == 0) {
            int r0 = rbase + f * 16 + g;
            g_part[cg][r0]     = s[f][0];
            g_part[cg][r0 + 8] = s[f][1];
        }
    }

    // last colgroup block for this rowgroup reduces partials -> g_rowc
    __syncthreads();
    if (threadIdx.x == 0) {
        __threadfence();
        sLast = (atomicAdd(&g_cnt[rg], 1) == NCG - 1);
    }
    __syncthreads();
    if (sLast) {
        __threadfence();
        int row = rg * ORPB + threadIdx.x;
        float tot = 0.f;
        #pragma unroll 8
        for (int c = 0; c < NCG; c++) tot += __ldcg(&g_part[c][row]);
        g_rowc[row] = -(LN2 * lg2f(tot));
    }
}

// ---------------- Kernel 4 (pass 2): smem-staged out = logit - ln(sum) ----------------
__global__ void __launch_bounds__(256, 5) k_out(float* __restrict__ out) {
    __shared__ uint4 sVq[OPAIRS * 32];

    const int lane = threadIdx.x & 31, warp = threadIdx.x >> 5;
    const int g = lane >> 2, t = lane & 3;
    const int cg    = blockIdx.x;
    const int rbase = blockIdx.y * ORPB + warp * 32;

    {
        const uint4* src = g_Vq + cg * (OPAIRS * 32);
        for (int i = threadIdx.x; i < OPAIRS * 32; i += 256) sVq[i] = src[i];
    }

    uint32_t a[2][4];
    const uint32_t* H = (const uint32_t*)g_hidden;
    float nc[2][2];
    #pragma unroll
    for (int f = 0; f < 2; f++) {
        int r0 = rbase + f * 16 + g;
        a[f][0] = H[r0 * 8 + t];
        a[f][1] = H[(r0 + 8) * 8 + t];
        a[f][2] = H[r0 * 8 + t + 4];
        a[f][3] = H[(r0 + 8) * 8 + t + 4];
        nc[f][0] = g_rowc[r0];
        nc[f][1] = g_rowc[r0 + 8];
    }
    __syncthreads();

    float* base = out + (size_t)(rbase + g) * VOCAB + cg * (OPAIRS * 16) + 4 * t;

    uint4 b = sVq[lane];
    #pragma unroll 1
    for (int pl = 0; pl < OPAIRS; pl++) {
        uint4 bn;
        if (pl + 1 < OPAIRS) bn = sVq[(pl + 1) * 32 + lane];
        float* bp = base + pl * 16;
        #pragma unroll
        for (int f = 0; f < 2; f++) {
            float d0[4], d1[4];
            mma16816c(d0, a[f], b.x, b.y, nc[f][0], nc[f][1]);
            mma16816c(d1, a[f], b.z, b.w, nc[f][0], nc[f][1]);
            __stcs((float4*)(bp + (size_t)(f * 16)     * VOCAB),
                   make_float4(d0[0], d0[1], d1[0], d1[1]));
            __stcs((float4*)(bp + (size_t)(f * 16 + 8) * VOCAB),
                   make_float4(d0[2], d0[3], d1[2], d1[3]));
        }
        b = bn;
    }
}

extern "C" void kernel_launch(void* const* d_in, const int* in_sizes, int n_in,
                              void* d_out, int out_size) {
    const int*   tok = (const int*)d_in[0];
    const float* emb = (const float*)d_in[1];
    const float* U   = (const float*)d_in[2];
    const float* W   = (const float*)d_in[3];
    const float* V   = (const float*)d_in[4];
    const float* b1  = (const float*)d_in[5];
    const float* b2  = (const float*)d_in[6];
    const float* h0  = (const float*)d_in[7];
    float* out = (float*)d_out;

    k_prepA<<<PREP_ABLK, 256>>>(tok, emb, U, b1, b2);
    k_mix<<<MIX_NBLK, 256>>>(V, W, h0);
    dim3 gs(NCG, NRG);
    k_sum<<<gs, 256>>>();
    k_out<<<gs, 256>>>(out);
}